// round 15
// baseline (speedup 1.0000x reference)
#include <cuda_runtime.h>

#define BB  2
#define NN  50000
#define EE  800000
#define FF  16
#define EMBD 32
#define BNE (BB*NN*EMBD)
#define FULLM 0xffffffffu
#define WPAD 36   // padded row stride for transposed weights (16B-aligned)

// ---------------- scratch ----------------
__device__ float g_x [BNE];
__device__ float g_A [2*BNE];
__device__ float g_Bt[2*BNE];
__device__ int   g_deg[NN];
__device__ int   g_rowptr[NN+1];
__device__ int   g_cursor[NN];
__device__ int2  g_edge[EE];        // (src, ew bits), dst-sorted
__device__ float g_gsum[BB*EMBD];
__device__ int   g_bsum[64];
__device__ float g_d4[BB*2*64*64];

// ---------------- CSR degree count ----------------
// relies on g_deg being zero on entry: zero-initialized at load, and k_scan1
// re-zeroes it after consuming, so the invariant holds for every call/replay.
__global__ void k_deg(const int* __restrict__ dst){
    int e = blockIdx.x*blockDim.x + threadIdx.x;
    if (e < EE) atomicAdd(&g_deg[dst[e]], 1);
}

// ---------------- scan phase 1: block-local inclusive scan ----------------
__global__ __launch_bounds__(1024) void k_scan1(){
    int tid = threadIdx.x, lane = tid & 31, wid = tid >> 5;
    int i = blockIdx.x*1024 + tid;
    int v = (i < NN) ? g_deg[i] : 0;
    if (i < NN){ g_deg[i] = 0; g_cursor[i] = 0; }
    if (blockIdx.x == 0 && tid < BB*EMBD) g_gsum[tid] = 0.f;
    int x = v;
    #pragma unroll
    for (int off = 1; off < 32; off <<= 1){
        int t = __shfl_up_sync(FULLM, x, off);
        if (lane >= off) x += t;
    }
    __shared__ int ws[32];
    if (lane == 31) ws[wid] = x;
    __syncthreads();
    if (wid == 0){
        int s = ws[lane];
        #pragma unroll
        for (int off = 1; off < 32; off <<= 1){
            int t = __shfl_up_sync(FULLM, s, off);
            if (lane >= off) s += t;
        }
        ws[lane] = s;
    }
    __syncthreads();
    int incl = x + (wid ? ws[wid-1] : 0);
    if (i < NN) g_rowptr[i+1] = incl;
    if (tid == 1023) g_bsum[blockIdx.x] = incl;
}

// ---------------- scan phase 2+3 fused ----------------
__global__ __launch_bounds__(1024) void k_scan23(){
    __shared__ int s_off;
    int tid = threadIdx.x, blk = blockIdx.x;
    if (tid < 32){
        int sum = 0;
        for (int i = tid; i < blk; i += 32) sum += g_bsum[i];
        #pragma unroll
        for (int off = 16; off > 0; off >>= 1)
            sum += __shfl_xor_sync(FULLM, sum, off);
        if (tid == 0) s_off = sum;
    }
    __syncthreads();
    int i = blk*1024 + tid;
    if (i < NN) g_rowptr[i+1] += s_off;
    if (i == 0) g_rowptr[0] = 0;
}

// ---------------- scatter edges into CSR (packed int2) ----------------
__global__ void k_scatter(const int* __restrict__ src, const int* __restrict__ dst,
                          const float* __restrict__ ew){
    int e = blockIdx.x*blockDim.x + threadIdx.x;
    if (e < EE){
        int d   = dst[e];
        int pos = g_rowptr[d] + atomicAdd(&g_cursor[d], 1);
        g_edge[pos] = make_int2(src[e], __float_as_int(ew[e]));
    }
}

// ---------------- projection + layer-0 A/Bt ----------------
__global__ __launch_bounds__(256) void k_proj(const float* __restrict__ nf,
        const float* __restrict__ pw, const float* __restrict__ pb,
        const float* __restrict__ msgw, const float* __restrict__ msgb){
    __shared__ float sP[FF*EMBD], sW1[EMBD*EMBD], sW2[EMBD*EMBD], sPB[EMBD], sMB[EMBD];
    int tid = threadIdx.x;
    for (int t = tid; t < FF*EMBD; t += 256) sP[t] = pw[t];
    for (int t = tid; t < EMBD*EMBD; t += 256){ sW1[t] = msgw[t]; sW2[t] = msgw[EMBD*EMBD + t]; }
    if (tid < EMBD){ sPB[tid] = pb[tid]; sMB[tid] = msgb[tid]; }
    __syncthreads();
    int lane = tid & 31;
    int n = blockIdx.x*8 + (tid >> 5);
    if (n >= NN) return;
    #pragma unroll
    for (int b = 0; b < BB; b++){
        float f = (lane < FF) ? nf[(b*NN + n)*FF + lane] : 0.f;
        float xv = sPB[lane];
        #pragma unroll
        for (int k = 0; k < FF; k++){
            float fk = __shfl_sync(FULLM, f, k);
            xv = fmaf(fk, sP[k*EMBD + lane], xv);
        }
        int base = n*(BB*EMBD) + b*EMBD + lane;
        g_x[base] = xv;
        float av = 0.f, bv = sMB[lane];
        #pragma unroll
        for (int k = 0; k < EMBD; k++){
            float xk = __shfl_sync(FULLM, xv, k);
            av = fmaf(xk, sW1[k*EMBD + lane], av);
            bv = fmaf(xk, sW2[k*EMBD + lane], bv);
        }
        g_A[base] = av; g_Bt[base] = bv;
    }
}

// ---------------- per-node gather (half-warp-alternating edges, whole warp one node) ----------------
__device__ __forceinline__ float4 gather_node(const float* __restrict__ A,
        const float* __restrict__ Bt, const int2* __restrict__ EV,
        int n, int qoff, float4 w34, int h){
    int r0 = g_rowptr[n], r1 = g_rowptr[n+1];
    float inv = 1.0f / (float)max(r1 - r0, 1);
    float4 bt4 = *(const float4*)(Bt + n*64 + qoff);
    float4 acc = make_float4(0.f, 0.f, 0.f, 0.f);
    for (int e = r0; e < r1; e += 8){
        float4 a[4]; float wwv[4]; bool act[4];
        #pragma unroll
        for (int u = 0; u < 4; u++){
            int jj = e + 2*u + h;
            act[u] = (jj < r1);
            if (act[u]){
                int2 ev = EV[jj];                 // broadcast within half-warp
                wwv[u] = __int_as_float(ev.y);
                a[u] = *(const float4*)(A + ev.x*64 + qoff);
            }
        }
        #pragma unroll
        for (int u = 0; u < 4; u++) if (act[u]){
            acc.x += fmaxf(fmaf(wwv[u], w34.x, bt4.x) + a[u].x, 0.f);
            acc.y += fmaxf(fmaf(wwv[u], w34.y, bt4.y) + a[u].y, 0.f);
            acc.z += fmaxf(fmaf(wwv[u], w34.z, bt4.z) + a[u].z, 0.f);
            acc.w += fmaxf(fmaf(wwv[u], w34.w, bt4.w) + a[u].w, 0.f);
        }
    }
    acc.x += __shfl_xor_sync(FULLM, acc.x, 16);
    acc.y += __shfl_xor_sync(FULLM, acc.y, 16);
    acc.z += __shfl_xor_sync(FULLM, acc.z, 16);
    acc.w += __shfl_xor_sync(FULLM, acc.w, 16);
    acc.x *= inv; acc.y *= inv; acc.z *= inv; acc.w *= inv;
    return acc;
}

// ---------------- fused layer: gather + update + next A/Bt (+ mean at l==2) ----------------
// 8 warps/block, 8 nodes/warp processed in PAIRS so each weight LDS.128 feeds 2 nodes.
__global__ __launch_bounds__(256) void k_layer(int l,
        const float* __restrict__ msgw, const float* __restrict__ msgb,
        const float* __restrict__ updw, const float* __restrict__ updb){
    __shared__ float sU1t[32*WPAD], sU2t[32*WPAD], sW1t[32*WPAD], sW2t[32*WPAD];
    __shared__ float sUB[32], sW3s[32], sMBn[32];
    __shared__ float sStage[8][256];   // per warp: n0:{x[0:64],agg[64:128]} n1:{x[128:192],agg[192:256]}
    __shared__ float sMean[64];
    int tid = threadIdx.x;
    const float* uw = updw + l*2048;
    for (int t = tid; t < 1024; t += 256){
        int k = t >> 5, j = t & 31;
        sU1t[j*WPAD + k] = uw[t];
        sU2t[j*WPAD + k] = uw[1024 + t];
    }
    if (l < 2){
        const float* mw = msgw + (l+1)*2080;
        for (int t = tid; t < 1024; t += 256){
            int k = t >> 5, j = t & 31;
            sW1t[j*WPAD + k] = mw[t];
            sW2t[j*WPAD + k] = mw[1024 + t];
        }
        if (tid < 32) sMBn[tid] = msgb[(l+1)*32 + tid];
    } else {
        if (tid < 64) sMean[tid] = 0.f;
    }
    if (tid < 32){ sUB[tid] = updb[l*32 + tid]; sW3s[tid] = msgw[l*2080 + 2048 + tid]; }
    __syncthreads();

    int lane = tid & 31, w = tid >> 5;
    int h = lane >> 4, q = lane & 15;
    int qoff = q*4, f0 = qoff & 31;
    float4 w34 = make_float4(sW3s[f0], sW3s[f0+1], sW3s[f0+2], sW3s[f0+3]);
    const float* __restrict__ A  = g_A  + (l & 1)*BNE;
    const float* __restrict__ Bt = g_Bt + (l & 1)*BNE;
    const int2* __restrict__ EV = g_edge;
    float* stg = sStage[w];
    int j = lane;
    float msum0 = 0.f, msum1 = 0.f;

    for (int it = 0; it < 4; it++){
        int n0 = blockIdx.x*64 + w*8 + it*2;
        if (n0 >= NN) break;
        int n1 = n0 + 1;
        bool has1 = (n1 < NN);
        int base0 = n0*64, base1 = n1*64;

        // ---- gather both nodes ----
        float4 ag0 = gather_node(A, Bt, EV, n0, qoff, w34, h);
        if (h == 0) *(float4*)(stg + 64 + qoff) = ag0;
        if (has1){
            float4 ag1 = gather_node(A, Bt, EV, n1, qoff, w34, h);
            if (h == 0) *(float4*)(stg + 192 + qoff) = ag1;
        }
        // ---- stage x for both nodes: one LDG.128/STS.128 per lane ----
        {
            int nb = h ? (has1 ? n1 : n0) : n0;
            *(float4*)(stg + h*128 + qoff) = *(const float4*)(g_x + nb*64 + qoff);
        }
        __syncwarp();

        // ---- paired update matvec ----
        float bub = sUB[j];
        float u0a = bub, u1a = bub, u0b = bub, u1b = bub;
        #pragma unroll
        for (int k = 0; k < 32; k += 4){
            float4 w1q = *(const float4*)(sU1t + j*WPAD + k);
            float4 w2q = *(const float4*)(sU2t + j*WPAD + k);
            float4 xa0 = *(const float4*)(stg + k);
            float4 xa1 = *(const float4*)(stg + 32 + k);
            float4 ga0 = *(const float4*)(stg + 64 + k);
            float4 ga1 = *(const float4*)(stg + 96 + k);
            u0a = fmaf(xa0.x, w1q.x, u0a); u0a = fmaf(ga0.x, w2q.x, u0a);
            u0a = fmaf(xa0.y, w1q.y, u0a); u0a = fmaf(ga0.y, w2q.y, u0a);
            u0a = fmaf(xa0.z, w1q.z, u0a); u0a = fmaf(ga0.z, w2q.z, u0a);
            u0a = fmaf(xa0.w, w1q.w, u0a); u0a = fmaf(ga0.w, w2q.w, u0a);
            u1a = fmaf(xa1.x, w1q.x, u1a); u1a = fmaf(ga1.x, w2q.x, u1a);
            u1a = fmaf(xa1.y, w1q.y, u1a); u1a = fmaf(ga1.y, w2q.y, u1a);
            u1a = fmaf(xa1.z, w1q.z, u1a); u1a = fmaf(ga1.z, w2q.z, u1a);
            u1a = fmaf(xa1.w, w1q.w, u1a); u1a = fmaf(ga1.w, w2q.w, u1a);
            float4 xb0 = *(const float4*)(stg + 128 + k);
            float4 xb1 = *(const float4*)(stg + 160 + k);
            float4 gb0 = *(const float4*)(stg + 192 + k);
            float4 gb1 = *(const float4*)(stg + 224 + k);
            u0b = fmaf(xb0.x, w1q.x, u0b); u0b = fmaf(gb0.x, w2q.x, u0b);
            u0b = fmaf(xb0.y, w1q.y, u0b); u0b = fmaf(gb0.y, w2q.y, u0b);
            u0b = fmaf(xb0.z, w1q.z, u0b); u0b = fmaf(gb0.z, w2q.z, u0b);
            u0b = fmaf(xb0.w, w1q.w, u0b); u0b = fmaf(gb0.w, w2q.w, u0b);
            u1b = fmaf(xb1.x, w1q.x, u1b); u1b = fmaf(gb1.x, w2q.x, u1b);
            u1b = fmaf(xb1.y, w1q.y, u1b); u1b = fmaf(gb1.y, w2q.y, u1b);
            u1b = fmaf(xb1.z, w1q.z, u1b); u1b = fmaf(gb1.z, w2q.z, u1b);
            u1b = fmaf(xb1.w, w1q.w, u1b); u1b = fmaf(gb1.w, w2q.w, u1b);
        }
        float xn0a = fmaxf(u0a, 0.f), xn1a = fmaxf(u1a, 0.f);
        float xn0b = fmaxf(u0b, 0.f), xn1b = fmaxf(u1b, 0.f);
        g_x[base0 + j] = xn0a; g_x[base0 + 32 + j] = xn1a;
        if (has1){ g_x[base1 + j] = xn0b; g_x[base1 + 32 + j] = xn1b; }

        if (l < 2){
            __syncwarp();
            stg[j] = xn0a; stg[32 + j] = xn1a;
            stg[128 + j] = xn0b; stg[160 + j] = xn1b;
            __syncwarp();
            int wsel = ((l+1) & 1)*BNE;
            float bmb = sMBn[j];
            float a0a = 0.f, a1a = 0.f, b0a = bmb, b1a = bmb;
            float a0b = 0.f, a1b = 0.f, b0b = bmb, b1b = bmb;
            #pragma unroll
            for (int k = 0; k < 32; k += 4){
                float4 w1q = *(const float4*)(sW1t + j*WPAD + k);
                float4 w2q = *(const float4*)(sW2t + j*WPAD + k);
                float4 xa0 = *(const float4*)(stg + k);
                float4 xa1 = *(const float4*)(stg + 32 + k);
                float4 xb0 = *(const float4*)(stg + 128 + k);
                float4 xb1 = *(const float4*)(stg + 160 + k);
                a0a = fmaf(xa0.x, w1q.x, a0a); b0a = fmaf(xa0.x, w2q.x, b0a);
                a0a = fmaf(xa0.y, w1q.y, a0a); b0a = fmaf(xa0.y, w2q.y, b0a);
                a0a = fmaf(xa0.z, w1q.z, a0a); b0a = fmaf(xa0.z, w2q.z, b0a);
                a0a = fmaf(xa0.w, w1q.w, a0a); b0a = fmaf(xa0.w, w2q.w, b0a);
                a1a = fmaf(xa1.x, w1q.x, a1a); b1a = fmaf(xa1.x, w2q.x, b1a);
                a1a = fmaf(xa1.y, w1q.y, a1a); b1a = fmaf(xa1.y, w2q.y, b1a);
                a1a = fmaf(xa1.z, w1q.z, a1a); b1a = fmaf(xa1.z, w2q.z, b1a);
                a1a = fmaf(xa1.w, w1q.w, a1a); b1a = fmaf(xa1.w, w2q.w, b1a);
                a0b = fmaf(xb0.x, w1q.x, a0b); b0b = fmaf(xb0.x, w2q.x, b0b);
                a0b = fmaf(xb0.y, w1q.y, a0b); b0b = fmaf(xb0.y, w2q.y, b0b);
                a0b = fmaf(xb0.z, w1q.z, a0b); b0b = fmaf(xb0.z, w2q.z, b0b);
                a0b = fmaf(xb0.w, w1q.w, a0b); b0b = fmaf(xb0.w, w2q.w, b0b);
                a1b = fmaf(xb1.x, w1q.x, a1b); b1b = fmaf(xb1.x, w2q.x, b1b);
                a1b = fmaf(xb1.y, w1q.y, a1b); b1b = fmaf(xb1.y, w2q.y, b1b);
                a1b = fmaf(xb1.z, w1q.z, a1b); b1b = fmaf(xb1.z, w2q.z, b1b);
                a1b = fmaf(xb1.w, w1q.w, a1b); b1b = fmaf(xb1.w, w2q.w, b1b);
            }
            g_A [wsel + base0 + j] = a0a; g_A [wsel + base0 + 32 + j] = a1a;
            g_Bt[wsel + base0 + j] = b0a; g_Bt[wsel + base0 + 32 + j] = b1a;
            if (has1){
                g_A [wsel + base1 + j] = a0b; g_A [wsel + base1 + 32 + j] = a1b;
                g_Bt[wsel + base1 + j] = b0b; g_Bt[wsel + base1 + 32 + j] = b1b;
            }
        } else {
            msum0 += xn0a + (has1 ? xn0b : 0.f);
            msum1 += xn1a + (has1 ? xn1b : 0.f);
        }
        __syncwarp();
    }

    if (l == 2){
        atomicAdd(&sMean[j], msum0);
        atomicAdd(&sMean[32 + j], msum1);
        __syncthreads();
        if (tid < 64) atomicAdd(&g_gsum[tid], sMean[tid]);
    }
}

// ---------------- fused tail: sniff + head + value + 5 deconvs + mask ----------------
__device__ __forceinline__ void deconv_sm(const float* __restrict__ in,
        const float* __restrict__ w, const float* __restrict__ bias,
        float* __restrict__ outp, int Cin, int Cout, int Hin, int tid){
    int Hout = Hin*2, total = Cout*Hout*Hout;
    for (int idx = tid; idx < total; idx += 1024){
        int x = idx % Hout;
        int y = (idx/Hout) % Hout;
        int o = idx/(Hout*Hout);
        float acc = bias[o];
        #pragma unroll
        for (int kh = 0; kh < 4; kh++){
            int ty = y + 1 - kh; if (ty < 0 || (ty & 1)) continue;
            int p = ty >> 1; if (p >= Hin) continue;
            #pragma unroll
            for (int kw = 0; kw < 4; kw++){
                int tx = x + 1 - kw; if (tx < 0 || (tx & 1)) continue;
                int q = tx >> 1; if (q >= Hin) continue;
                for (int i = 0; i < Cin; i++)
                    acc = fmaf(in[(i*Hin + p)*Hin + q],
                               w[((i*Cout + o)*4 + kh)*4 + kw], acc);
            }
        }
        outp[idx] = fmaxf(acc, 0.f);
    }
}

__global__ __launch_bounds__(1024) void k_tail(const int* __restrict__ macro_idx,
        const float* __restrict__ meta,
        const float* __restrict__ mw, const float* __restrict__ mb,
        const float* __restrict__ metw, const float* __restrict__ metb,
        const float* __restrict__ pw, const float* __restrict__ pb,
        const float* __restrict__ dcw1, const float* __restrict__ dcb1,
        const float* __restrict__ dcw2, const float* __restrict__ dcb2,
        const float* __restrict__ dcw3, const float* __restrict__ dcb3,
        const float* __restrict__ dcw4, const float* __restrict__ dcb4,
        const float* __restrict__ dcw5, const float* __restrict__ dcb5,
        const float* __restrict__ vw1, const float* __restrict__ vb1,
        const float* __restrict__ vw2, const float* __restrict__ vb2,
        const void* __restrict__ maskp, float* __restrict__ out){
    __shared__ float comb[80], v1s[32], h0s[512];
    __shared__ float bufA[4096], bufB[2048];
    __shared__ int s_badi, s_badf, s_mode;
    int b = blockIdx.x;
    int tid = threadIdx.x;

    if (tid == 0){ s_badi = 0; s_badf = 0; }
    __syncthreads();
    {   // mask dtype sniff (first 20000 bytes valid under all candidate dtypes)
        const unsigned int* m = (const unsigned int*)maskp;
        int li = 0, lf = 0;
        for (int i = tid; i < 5000; i += 1024){
            unsigned int v = m[i];
            if (v != 0u && v != 1u) li = 1;
            if (v != 0u && v != 0x3F800000u) lf = 1;
        }
        if (li) atomicOr(&s_badi, 1);
        if (lf) atomicOr(&s_badf, 1);
    }

    if (tid < 32){
        comb[tid] = g_gsum[b*32 + tid] * (1.0f/NN);
    } else if (tid < 64){
        int j = tid - 32;
        int mi = macro_idx[b];
        const float* xr = g_x + mi*64 + b*32;
        float acc = mb[j];
        for (int k = 0; k < 32; k++) acc = fmaf(xr[k], mw[k*32 + j], acc);
        comb[32 + j] = acc;
    } else if (tid < 80){
        int j = tid - 64;
        float acc = metb[j];
        for (int k = 0; k < 4; k++) acc = fmaf(meta[b*4 + k], metw[k*16 + j], acc);
        comb[64 + j] = fmaxf(acc, 0.f);
    }
    __syncthreads();
    if (tid == 0)
        s_mode = (!s_badi) ? 1 : ((!s_badf) ? 2 : 0);

    if (tid < 512){
        float acc = pb[tid];
        for (int k = 0; k < 80; k++) acc = fmaf(comb[k], pw[k*512 + tid], acc);
        h0s[tid] = fmaxf(acc, 0.f);
    } else if (tid < 544){
        int j = tid - 512;
        float acc = vb1[j];
        for (int k = 0; k < 80; k++) acc = fmaf(comb[k], vw1[k*32 + j], acc);
        v1s[j] = fmaxf(acc, 0.f);
    }
    __syncthreads();
    if (tid == 544){
        float acc = vb2[0];
        for (int k = 0; k < 32; k++) acc = fmaf(v1s[k], vw2[k], acc);
        out[20000 + b] = acc;
    }

    deconv_sm(h0s,  dcw1, dcb1, bufA, 32, 16,  4, tid); __syncthreads();
    deconv_sm(bufA, dcw2, dcb2, bufB, 16,  8,  8, tid); __syncthreads();
    deconv_sm(bufB, dcw3, dcb3, bufA,  8,  4, 16, tid); __syncthreads();
    float* d4 = g_d4 + b*8192;
    deconv_sm(bufA, dcw4, dcb4, d4,    4,  2, 32, tid); __syncthreads();

    int mode = s_mode;
    for (int idx = tid; idx < 10000; idx += 1024){
        int x = idx % 100, y = idx / 100;
        float acc = dcb5[0];
        #pragma unroll
        for (int kh = 0; kh < 4; kh++){
            int ty = y + 1 - kh; if (ty < 0 || (ty & 1)) continue;
            int p = ty >> 1; if (p >= 64) continue;
            #pragma unroll
            for (int kw = 0; kw < 4; kw++){
                int tx = x + 1 - kw; if (tx < 0 || (tx & 1)) continue;
                int q = tx >> 1; if (q >= 64) continue;
                acc = fmaf(d4[p*64 + q],        dcw5[kh*4 + kw],      acc);
                acc = fmaf(d4[4096 + p*64 + q], dcw5[16 + kh*4 + kw], acc);
            }
        }
        int gidx = b*10000 + idx;
        bool mv;
        if (mode == 1)      mv = ((const int*)maskp)[gidx] != 0;
        else if (mode == 2) mv = ((const float*)maskp)[gidx] != 0.0f;
        else                mv = ((const unsigned char*)maskp)[gidx] != 0;
        out[gidx] = mv ? acc : -100000000.0f;
    }
}

// ---------------- launch ----------------
extern "C" void kernel_launch(void* const* d_in, const int* in_sizes, int n_in,
                              void* d_out, int out_size){
    const float* nf   = (const float*)d_in[0];
    const int*   ei   = (const int*)  d_in[1];
    const float* ew   = (const float*)d_in[2];
    const int*   midx = (const int*)  d_in[3];
    const float* meta = (const float*)d_in[4];
    const void*  mask = (const void*) d_in[5];
    const float* pw   = (const float*)d_in[6];
    const float* pbb  = (const float*)d_in[7];
    const float* msgw = (const float*)d_in[8];
    const float* msgb = (const float*)d_in[9];
    const float* updw = (const float*)d_in[10];
    const float* updb = (const float*)d_in[11];
    const float* macw = (const float*)d_in[12];
    const float* macb = (const float*)d_in[13];
    const float* metw = (const float*)d_in[14];
    const float* metb = (const float*)d_in[15];
    const float* polw = (const float*)d_in[16];
    const float* polb = (const float*)d_in[17];
    const float* dcw1 = (const float*)d_in[18];
    const float* dcb1 = (const float*)d_in[19];
    const float* dcw2 = (const float*)d_in[20];
    const float* dcb2 = (const float*)d_in[21];
    const float* dcw3 = (const float*)d_in[22];
    const float* dcb3 = (const float*)d_in[23];
    const float* dcw4 = (const float*)d_in[24];
    const float* dcb4 = (const float*)d_in[25];
    const float* dcw5 = (const float*)d_in[26];
    const float* dcb5 = (const float*)d_in[27];
    const float* vw1  = (const float*)d_in[28];
    const float* vb1  = (const float*)d_in[29];
    const float* vw2  = (const float*)d_in[30];
    const float* vb2  = (const float*)d_in[31];
    float* out = (float*)d_out;

    const int* src = ei;
    const int* dst = ei + EE;

    k_deg    <<<(EE+255)/256, 256>>>(dst);
    k_scan1  <<<49, 1024>>>();
    k_scan23 <<<49, 1024>>>();
    k_scatter<<<(EE+255)/256, 256>>>(src, dst, ew);
    k_proj   <<<(NN+7)/8, 256>>>(nf, pw, pbb, msgw, msgb);
    for (int l = 0; l < 3; l++)
        k_layer<<<(NN+63)/64, 256>>>(l, msgw, msgb, updw, updb);
    k_tail<<<2, 1024>>>(midx, meta, macw, macb, metw, metb, polw, polb,
                        dcw1, dcb1, dcw2, dcb2, dcw3, dcb3, dcw4, dcb4, dcw5, dcb5,
                        vw1, vb1, vw2, vb2, mask, out);
}

// round 16
// speedup vs baseline: 1.3760x; 1.3760x over previous
#include <cuda_runtime.h>

#define BB  2
#define NN  50000
#define EE  800000
#define FF  16
#define EMBD 32
#define BNE (BB*NN*EMBD)
#define FULLM 0xffffffffu
#define WPAD 36   // padded row stride for transposed weights (16B-aligned)

// ---------------- scratch ----------------
__device__ float g_x [BNE];
__device__ float g_A [2*BNE];
__device__ float g_Bt[2*BNE];
__device__ int   g_deg[NN];
__device__ int   g_rowptr[NN+1];
__device__ int   g_cursor[NN];
__device__ int2  g_edge[EE];        // (src, ew bits), dst-sorted
__device__ float g_gsum[BB*EMBD];
__device__ int   g_bsum[64];
__device__ float g_d4[BB*2*64*64];

// ---------------- CSR degree count ----------------
// g_deg is zero on entry: zero-initialized at load, and k_scan1 re-zeroes it
// after consuming, so the invariant holds for every call/replay.
__global__ void k_deg(const int* __restrict__ dst){
    int e = blockIdx.x*blockDim.x + threadIdx.x;
    if (e < EE) atomicAdd(&g_deg[dst[e]], 1);
}

// ---------------- scan phase 1: block-local inclusive scan ----------------
__global__ __launch_bounds__(1024) void k_scan1(){
    int tid = threadIdx.x, lane = tid & 31, wid = tid >> 5;
    int i = blockIdx.x*1024 + tid;
    int v = (i < NN) ? g_deg[i] : 0;
    if (i < NN){ g_deg[i] = 0; g_cursor[i] = 0; }
    if (blockIdx.x == 0 && tid < BB*EMBD) g_gsum[tid] = 0.f;
    int x = v;
    #pragma unroll
    for (int off = 1; off < 32; off <<= 1){
        int t = __shfl_up_sync(FULLM, x, off);
        if (lane >= off) x += t;
    }
    __shared__ int ws[32];
    if (lane == 31) ws[wid] = x;
    __syncthreads();
    if (wid == 0){
        int s = ws[lane];
        #pragma unroll
        for (int off = 1; off < 32; off <<= 1){
            int t = __shfl_up_sync(FULLM, s, off);
            if (lane >= off) s += t;
        }
        ws[lane] = s;
    }
    __syncthreads();
    int incl = x + (wid ? ws[wid-1] : 0);
    if (i < NN) g_rowptr[i+1] = incl;
    if (tid == 1023) g_bsum[blockIdx.x] = incl;
}

// ---------------- scan phase 2+3 fused ----------------
__global__ __launch_bounds__(1024) void k_scan23(){
    __shared__ int s_off;
    int tid = threadIdx.x, blk = blockIdx.x;
    if (tid < 32){
        int sum = 0;
        for (int i = tid; i < blk; i += 32) sum += g_bsum[i];
        #pragma unroll
        for (int off = 16; off > 0; off >>= 1)
            sum += __shfl_xor_sync(FULLM, sum, off);
        if (tid == 0) s_off = sum;
    }
    __syncthreads();
    int i = blk*1024 + tid;
    if (i < NN) g_rowptr[i+1] += s_off;
    if (i == 0) g_rowptr[0] = 0;
}

// ---------------- scatter edges into CSR (packed int2) ----------------
__global__ void k_scatter(const int* __restrict__ src, const int* __restrict__ dst,
                          const float* __restrict__ ew){
    int e = blockIdx.x*blockDim.x + threadIdx.x;
    if (e < EE){
        int d   = dst[e];
        int pos = g_rowptr[d] + atomicAdd(&g_cursor[d], 1);
        g_edge[pos] = make_int2(src[e], __float_as_int(ew[e]));
    }
}

// ---------------- projection + layer-0 A/Bt ----------------
__global__ __launch_bounds__(256) void k_proj(const float* __restrict__ nf,
        const float* __restrict__ pw, const float* __restrict__ pb,
        const float* __restrict__ msgw, const float* __restrict__ msgb){
    __shared__ float sP[FF*EMBD], sW1[EMBD*EMBD], sW2[EMBD*EMBD], sPB[EMBD], sMB[EMBD];
    int tid = threadIdx.x;
    for (int t = tid; t < FF*EMBD; t += 256) sP[t] = pw[t];
    for (int t = tid; t < EMBD*EMBD; t += 256){ sW1[t] = msgw[t]; sW2[t] = msgw[EMBD*EMBD + t]; }
    if (tid < EMBD){ sPB[tid] = pb[tid]; sMB[tid] = msgb[tid]; }
    __syncthreads();
    int lane = tid & 31;
    int n = blockIdx.x*8 + (tid >> 5);
    if (n >= NN) return;
    #pragma unroll
    for (int b = 0; b < BB; b++){
        float f = (lane < FF) ? nf[(b*NN + n)*FF + lane] : 0.f;
        float xv = sPB[lane];
        #pragma unroll
        for (int k = 0; k < FF; k++){
            float fk = __shfl_sync(FULLM, f, k);
            xv = fmaf(fk, sP[k*EMBD + lane], xv);
        }
        int base = n*(BB*EMBD) + b*EMBD + lane;
        g_x[base] = xv;
        float av = 0.f, bv = sMB[lane];
        #pragma unroll
        for (int k = 0; k < EMBD; k++){
            float xk = __shfl_sync(FULLM, xv, k);
            av = fmaf(xk, sW1[k*EMBD + lane], av);
            bv = fmaf(xk, sW2[k*EMBD + lane], bv);
        }
        g_A[base] = av; g_Bt[base] = bv;
    }
}

// ---------------- aggregation + update (+ next-layer A/Bt, mean at l==2) ----------------
// 8 warps/block, 8 nodes per warp. Gather: shfl-free half-warp broadcast loads.
// Epilogue: smem-staged x/agg + TRANSPOSED weights -> LDS.128 everywhere, no shfl.
__global__ __launch_bounds__(256) void k_layer(int l,
        const float* __restrict__ msgw, const float* __restrict__ msgb,
        const float* __restrict__ updw, const float* __restrict__ updb){
    __shared__ float sU1t[32*WPAD], sU2t[32*WPAD], sW1t[32*WPAD], sW2t[32*WPAD];
    __shared__ float sUB[32], sW3[32], sMBn[32];
    __shared__ float sStage[8][128];   // per warp: [0:64]=x record, [64:128]=agg record
    __shared__ float sMean[64];
    int tid = threadIdx.x;
    const float* uw = updw + l*2048;
    // transposed weight fill: Wt[j*WPAD + k] = W[k*32 + j]
    for (int t = tid; t < 1024; t += 256){
        int k = t >> 5, j = t & 31;
        sU1t[j*WPAD + k] = uw[t];
        sU2t[j*WPAD + k] = uw[1024 + t];
    }
    if (l < 2){
        const float* mw = msgw + (l+1)*2080;
        for (int t = tid; t < 1024; t += 256){
            int k = t >> 5, j = t & 31;
            sW1t[j*WPAD + k] = mw[t];
            sW2t[j*WPAD + k] = mw[1024 + t];
        }
        if (tid < 32) sMBn[tid] = msgb[(l+1)*32 + tid];
    } else {
        if (tid < 64) sMean[tid] = 0.f;
    }
    if (tid < 32){ sUB[tid] = updb[l*32 + tid]; sW3[tid] = msgw[l*2080 + 2048 + tid]; }
    __syncthreads();

    int lane = tid & 31, w = tid >> 5;
    int h = lane >> 4, q = lane & 15;
    int qoff = q*4;
    int f0 = qoff & 31;
    float4 w34 = make_float4(sW3[f0], sW3[f0+1], sW3[f0+2], sW3[f0+3]);
    const float* __restrict__ A  = g_A  + (l & 1)*BNE;
    const float* __restrict__ Bt = g_Bt + (l & 1)*BNE;
    const int2* __restrict__ EV = g_edge;
    float* stg = sStage[w];
    int j = lane;
    float msum0 = 0.f, msum1 = 0.f;

    for (int it = 0; it < 8; it++){
        int n = blockIdx.x*64 + w*8 + it;
        if (n >= NN) break;
        int r0 = g_rowptr[n], r1 = g_rowptr[n+1];
        float inv = 1.0f / (float)max(r1 - r0, 1);
        int base = n*64;

        // ---- gather ----
        float4 bt4 = *(const float4*)(Bt + base + qoff);
        float4 acc = make_float4(0.f, 0.f, 0.f, 0.f);
        for (int e2 = r0; e2 < r1; e2 += 8){
            float4 a[4]; float wwv[4]; bool act[4];
            #pragma unroll
            for (int u = 0; u < 4; u++){
                int jj = e2 + 2*u + h;
                act[u] = (jj < r1);
                if (act[u]){
                    int2 ev = EV[jj];
                    wwv[u] = __int_as_float(ev.y);
                    a[u] = *(const float4*)(A + ev.x*64 + qoff);
                }
            }
            #pragma unroll
            for (int u = 0; u < 4; u++) if (act[u]){
                acc.x += fmaxf(a[u].x + bt4.x + wwv[u]*w34.x, 0.f);
                acc.y += fmaxf(a[u].y + bt4.y + wwv[u]*w34.y, 0.f);
                acc.z += fmaxf(a[u].z + bt4.z + wwv[u]*w34.z, 0.f);
                acc.w += fmaxf(a[u].w + bt4.w + wwv[u]*w34.w, 0.f);
            }
        }
        acc.x += __shfl_xor_sync(FULLM, acc.x, 16);
        acc.y += __shfl_xor_sync(FULLM, acc.y, 16);
        acc.z += __shfl_xor_sync(FULLM, acc.z, 16);
        acc.w += __shfl_xor_sync(FULLM, acc.w, 16);
        acc.x *= inv; acc.y *= inv; acc.z *= inv; acc.w *= inv;
        if (h == 0) *(float4*)(stg + 64 + qoff) = acc;   // agg record
        // stage x record
        stg[j]      = g_x[base + j];
        stg[32 + j] = g_x[base + 32 + j];
        __syncwarp();

        // ---- update matvec: u = W1^T x + W2^T agg + b (both batches) ----
        float u0 = sUB[j], u1 = u0;
        #pragma unroll
        for (int k = 0; k < 32; k += 4){
            float4 xq0 = *(const float4*)(stg + k);
            float4 xq1 = *(const float4*)(stg + 32 + k);
            float4 gq0 = *(const float4*)(stg + 64 + k);
            float4 gq1 = *(const float4*)(stg + 96 + k);
            float4 w1q = *(const float4*)(sU1t + j*WPAD + k);
            float4 w2q = *(const float4*)(sU2t + j*WPAD + k);
            u0 = fmaf(xq0.x, w1q.x, u0); u0 = fmaf(gq0.x, w2q.x, u0);
            u0 = fmaf(xq0.y, w1q.y, u0); u0 = fmaf(gq0.y, w2q.y, u0);
            u0 = fmaf(xq0.z, w1q.z, u0); u0 = fmaf(gq0.z, w2q.z, u0);
            u0 = fmaf(xq0.w, w1q.w, u0); u0 = fmaf(gq0.w, w2q.w, u0);
            u1 = fmaf(xq1.x, w1q.x, u1); u1 = fmaf(gq1.x, w2q.x, u1);
            u1 = fmaf(xq1.y, w1q.y, u1); u1 = fmaf(gq1.y, w2q.y, u1);
            u1 = fmaf(xq1.z, w1q.z, u1); u1 = fmaf(gq1.z, w2q.z, u1);
            u1 = fmaf(xq1.w, w1q.w, u1); u1 = fmaf(gq1.w, w2q.w, u1);
        }
        float xn0 = fmaxf(u0, 0.f), xn1 = fmaxf(u1, 0.f);
        g_x[base + j] = xn0; g_x[base + 32 + j] = xn1;

        if (l < 2){
            __syncwarp();
            stg[j] = xn0; stg[32 + j] = xn1;
            __syncwarp();
            int wsel = ((l+1) & 1)*BNE;
            float a0 = 0.f, a1 = 0.f, b0 = sMBn[j], b1 = b0;
            #pragma unroll
            for (int k = 0; k < 32; k += 4){
                float4 xq0 = *(const float4*)(stg + k);
                float4 xq1 = *(const float4*)(stg + 32 + k);
                float4 w1q = *(const float4*)(sW1t + j*WPAD + k);
                float4 w2q = *(const float4*)(sW2t + j*WPAD + k);
                a0 = fmaf(xq0.x, w1q.x, a0); b0 = fmaf(xq0.x, w2q.x, b0);
                a0 = fmaf(xq0.y, w1q.y, a0); b0 = fmaf(xq0.y, w2q.y, b0);
                a0 = fmaf(xq0.z, w1q.z, a0); b0 = fmaf(xq0.z, w2q.z, b0);
                a0 = fmaf(xq0.w, w1q.w, a0); b0 = fmaf(xq0.w, w2q.w, b0);
                a1 = fmaf(xq1.x, w1q.x, a1); b1 = fmaf(xq1.x, w2q.x, b1);
                a1 = fmaf(xq1.y, w1q.y, a1); b1 = fmaf(xq1.y, w2q.y, b1);
                a1 = fmaf(xq1.z, w1q.z, a1); b1 = fmaf(xq1.z, w2q.z, b1);
                a1 = fmaf(xq1.w, w1q.w, a1); b1 = fmaf(xq1.w, w2q.w, b1);
            }
            g_A [wsel + base + j] = a0; g_A [wsel + base + 32 + j] = a1;
            g_Bt[wsel + base + j] = b0; g_Bt[wsel + base + 32 + j] = b1;
        } else {
            msum0 += xn0; msum1 += xn1;
        }
        __syncwarp();
    }

    if (l == 2){
        atomicAdd(&sMean[j], msum0);
        atomicAdd(&sMean[32 + j], msum1);
        __syncthreads();
        if (tid < 64) atomicAdd(&g_gsum[tid], sMean[tid]);
    }
}

// ---------------- fused tail: sniff + head + value + 5 deconvs + mask ----------------
__device__ __forceinline__ void deconv_sm(const float* __restrict__ in,
        const float* __restrict__ w, const float* __restrict__ bias,
        float* __restrict__ outp, int Cin, int Cout, int Hin, int tid){
    int Hout = Hin*2, total = Cout*Hout*Hout;
    for (int idx = tid; idx < total; idx += 1024){
        int x = idx % Hout;
        int y = (idx/Hout) % Hout;
        int o = idx/(Hout*Hout);
        float acc = bias[o];
        #pragma unroll
        for (int kh = 0; kh < 4; kh++){
            int ty = y + 1 - kh; if (ty < 0 || (ty & 1)) continue;
            int p = ty >> 1; if (p >= Hin) continue;
            #pragma unroll
            for (int kw = 0; kw < 4; kw++){
                int tx = x + 1 - kw; if (tx < 0 || (tx & 1)) continue;
                int q = tx >> 1; if (q >= Hin) continue;
                for (int i = 0; i < Cin; i++)
                    acc = fmaf(in[(i*Hin + p)*Hin + q],
                               w[((i*Cout + o)*4 + kh)*4 + kw], acc);
            }
        }
        outp[idx] = fmaxf(acc, 0.f);
    }
}

__global__ __launch_bounds__(1024) void k_tail(const int* __restrict__ macro_idx,
        const float* __restrict__ meta,
        const float* __restrict__ mw, const float* __restrict__ mb,
        const float* __restrict__ metw, const float* __restrict__ metb,
        const float* __restrict__ pw, const float* __restrict__ pb,
        const float* __restrict__ dcw1, const float* __restrict__ dcb1,
        const float* __restrict__ dcw2, const float* __restrict__ dcb2,
        const float* __restrict__ dcw3, const float* __restrict__ dcb3,
        const float* __restrict__ dcw4, const float* __restrict__ dcb4,
        const float* __restrict__ dcw5, const float* __restrict__ dcb5,
        const float* __restrict__ vw1, const float* __restrict__ vb1,
        const float* __restrict__ vw2, const float* __restrict__ vb2,
        const void* __restrict__ maskp, float* __restrict__ out){
    __shared__ float comb[80], v1s[32], h0s[512];
    __shared__ float bufA[4096], bufB[2048];
    __shared__ int s_badi, s_badf, s_mode;
    int b = blockIdx.x;
    int tid = threadIdx.x;

    if (tid == 0){ s_badi = 0; s_badf = 0; }
    __syncthreads();
    {   // mask dtype sniff (first 20000 bytes valid under all candidate dtypes)
        const unsigned int* m = (const unsigned int*)maskp;
        int li = 0, lf = 0;
        for (int i = tid; i < 5000; i += 1024){
            unsigned int v = m[i];
            if (v != 0u && v != 1u) li = 1;
            if (v != 0u && v != 0x3F800000u) lf = 1;
        }
        if (li) atomicOr(&s_badi, 1);
        if (lf) atomicOr(&s_badf, 1);
    }

    if (tid < 32){
        comb[tid] = g_gsum[b*32 + tid] * (1.0f/NN);
    } else if (tid < 64){
        int j = tid - 32;
        int mi = macro_idx[b];
        const float* xr = g_x + mi*64 + b*32;
        float acc = mb[j];
        for (int k = 0; k < 32; k++) acc = fmaf(xr[k], mw[k*32 + j], acc);
        comb[32 + j] = acc;
    } else if (tid < 80){
        int j = tid - 64;
        float acc = metb[j];
        for (int k = 0; k < 4; k++) acc = fmaf(meta[b*4 + k], metw[k*16 + j], acc);
        comb[64 + j] = fmaxf(acc, 0.f);
    }
    __syncthreads();
    if (tid == 0)
        s_mode = (!s_badi) ? 1 : ((!s_badf) ? 2 : 0);

    if (tid < 512){
        float acc = pb[tid];
        for (int k = 0; k < 80; k++) acc = fmaf(comb[k], pw[k*512 + tid], acc);
        h0s[tid] = fmaxf(acc, 0.f);
    } else if (tid < 544){
        int j = tid - 512;
        float acc = vb1[j];
        for (int k = 0; k < 80; k++) acc = fmaf(comb[k], vw1[k*32 + j], acc);
        v1s[j] = fmaxf(acc, 0.f);
    }
    __syncthreads();
    if (tid == 544){
        float acc = vb2[0];
        for (int k = 0; k < 32; k++) acc = fmaf(v1s[k], vw2[k], acc);
        out[20000 + b] = acc;
    }

    deconv_sm(h0s,  dcw1, dcb1, bufA, 32, 16,  4, tid); __syncthreads();
    deconv_sm(bufA, dcw2, dcb2, bufB, 16,  8,  8, tid); __syncthreads();
    deconv_sm(bufB, dcw3, dcb3, bufA,  8,  4, 16, tid); __syncthreads();
    float* d4 = g_d4 + b*8192;
    deconv_sm(bufA, dcw4, dcb4, d4,    4,  2, 32, tid); __syncthreads();

    int mode = s_mode;
    for (int idx = tid; idx < 10000; idx += 1024){
        int x = idx % 100, y = idx / 100;
        float acc = dcb5[0];
        #pragma unroll
        for (int kh = 0; kh < 4; kh++){
            int ty = y + 1 - kh; if (ty < 0 || (ty & 1)) continue;
            int p = ty >> 1; if (p >= 64) continue;
            #pragma unroll
            for (int kw = 0; kw < 4; kw++){
                int tx = x + 1 - kw; if (tx < 0 || (tx & 1)) continue;
                int q = tx >> 1; if (q >= 64) continue;
                acc = fmaf(d4[p*64 + q],        dcw5[kh*4 + kw],      acc);
                acc = fmaf(d4[4096 + p*64 + q], dcw5[16 + kh*4 + kw], acc);
            }
        }
        int gidx = b*10000 + idx;
        bool mv;
        if (mode == 1)      mv = ((const int*)maskp)[gidx] != 0;
        else if (mode == 2) mv = ((const float*)maskp)[gidx] != 0.0f;
        else                mv = ((const unsigned char*)maskp)[gidx] != 0;
        out[gidx] = mv ? acc : -100000000.0f;
    }
}

// ---------------- launch ----------------
extern "C" void kernel_launch(void* const* d_in, const int* in_sizes, int n_in,
                              void* d_out, int out_size){
    const float* nf   = (const float*)d_in[0];
    const int*   ei   = (const int*)  d_in[1];
    const float* ew   = (const float*)d_in[2];
    const int*   midx = (const int*)  d_in[3];
    const float* meta = (const float*)d_in[4];
    const void*  mask = (const void*) d_in[5];
    const float* pw   = (const float*)d_in[6];
    const float* pbb  = (const float*)d_in[7];
    const float* msgw = (const float*)d_in[8];
    const float* msgb = (const float*)d_in[9];
    const float* updw = (const float*)d_in[10];
    const float* updb = (const float*)d_in[11];
    const float* macw = (const float*)d_in[12];
    const float* macb = (const float*)d_in[13];
    const float* metw = (const float*)d_in[14];
    const float* metb = (const float*)d_in[15];
    const float* polw = (const float*)d_in[16];
    const float* polb = (const float*)d_in[17];
    const float* dcw1 = (const float*)d_in[18];
    const float* dcb1 = (const float*)d_in[19];
    const float* dcw2 = (const float*)d_in[20];
    const float* dcb2 = (const float*)d_in[21];
    const float* dcw3 = (const float*)d_in[22];
    const float* dcb3 = (const float*)d_in[23];
    const float* dcw4 = (const float*)d_in[24];
    const float* dcb4 = (const float*)d_in[25];
    const float* dcw5 = (const float*)d_in[26];
    const float* dcb5 = (const float*)d_in[27];
    const float* vw1  = (const float*)d_in[28];
    const float* vb1  = (const float*)d_in[29];
    const float* vw2  = (const float*)d_in[30];
    const float* vb2  = (const float*)d_in[31];
    float* out = (float*)d_out;

    const int* src = ei;
    const int* dst = ei + EE;

    k_deg    <<<(EE+255)/256, 256>>>(dst);
    k_scan1  <<<49, 1024>>>();
    k_scan23 <<<49, 1024>>>();
    k_scatter<<<(EE+255)/256, 256>>>(src, dst, ew);
    k_proj   <<<(NN+7)/8, 256>>>(nf, pw, pbb, msgw, msgb);
    for (int l = 0; l < 3; l++)
        k_layer<<<(NN+63)/64, 256>>>(l, msgw, msgb, updw, updb);
    k_tail<<<2, 1024>>>(midx, meta, macw, macb, metw, metb, polw, polb,
                        dcw1, dcb1, dcw2, dcb2, dcw3, dcb3, dcw4, dcb4, dcw5, dcb5,
                        vw1, vb1, vw2, vb2, mask, out);
}